// round 12
// baseline (speedup 1.0000x reference)
#include <cuda_runtime.h>
#include <cuda_fp16.h>
#include <cstdint>
#include <math.h>

// ---------------------------------------------------------------------------
// ColorHistogramMatchingLoss — R9 (resubmit; prior round was an infra failure)
// fp16 HMMA histogram GEMM (R8 mainloop: A hi/lo split stack, single fp16 B).
// R9: epilogue writes plain per-block partials (no L2 atomics — R8 showed
// ~125us of L2-atomic serialization); wide 192-block reduce (one float4 per
// thread, 64 independent LDG.128 -> MLP-rich, ~12us for 50MB).
// ---------------------------------------------------------------------------

#define NB        8
#define DH        64
#define CHUNKS    64
#define CHUNK_PIX 1024
#define SG_PIX    512
#define WIN       64
#define NWIN      (SG_PIX / WIN)      // 8
#define NPIX      65536
#define TOT_BLOCKS (2 * NB * 3 * CHUNKS)   // 3072
#define NHIST     (2 * NB * 3)             // 48

__device__ float g_part[(size_t)TOT_BLOCKS * DH * DH];   // 50.3 MB
__device__ float g_hist[(size_t)NHIST * DH * DH];
__device__ float g_bsum[NHIST * 4];

typedef unsigned long long ull;

// byte offsets in dynamic smem
#define UO 0
#define VO 2048
#define WO 4096
#define AO(bf) (6144 + (bf) * 24576)            // 128 rows x 128B = 16KB
#define BO(bf) (6144 + (bf) * 24576 + 16384)    // 64 rows x 128B = 8KB
#define EPIL   AO(0)
#define SMEM_BYTES (6144 + 2 * 24576)           // 55296

__device__ __forceinline__ uint32_t s2u(const void* p) {
    uint32_t a;
    asm("{ .reg .u64 t; cvta.to.shared.u64 t, %1; cvt.u32.u64 %0, t; }"
        : "=r"(a) : "l"(p));
    return a;
}
__device__ __forceinline__ float frcp(float x) {
    float r; asm("rcp.approx.ftz.f32 %0, %1;" : "=f"(r) : "f"(x)); return r;
}
__device__ __forceinline__ uint32_t packh2(float lo, float hi) {
    __half2 h = __floats2half2_rn(lo, hi);
    return *reinterpret_cast<uint32_t*>(&h);
}
__device__ __forceinline__ float2 unpackh2(uint32_t u) {
    __half2 h = *reinterpret_cast<__half2*>(&u);
    return __half22float2(h);
}
#define F2FMA(d, a, b, c) \
    asm("fma.rn.f32x2 %0, %1, %2, %3;" : "=l"(d) : "l"(a), "l"(b), "l"(c))
#define DUPU(d, u) \
    asm("mov.b64 %0, {%1, %1};" : "=l"(d) : "r"(u))
#define UNPK(lo, hi, v) \
    asm("mov.b64 {%0, %1}, %2;" : "=r"(lo), "=r"(hi) : "l"(v))

#define LDSM4(r, addr)                                                        \
    asm volatile("ldmatrix.sync.aligned.m8n8.x4.shared.b16 {%0,%1,%2,%3}, [%4];" \
                 : "=r"((r)[0]), "=r"((r)[1]), "=r"((r)[2]), "=r"((r)[3])     \
                 : "r"(addr))
#define STS32(addr, v) \
    asm volatile("st.shared.b32 [%0], %1;" :: "r"(addr), "r"(v) : "memory")

#define MMA(dd, a0, a1, a2, a3, b0, b1)                                       \
    asm volatile("mma.sync.aligned.m16n8k16.row.col.f32.f16.f16.f32 "         \
                 "{%0,%1,%2,%3}, {%4,%5,%6,%7}, {%8,%9}, {%0,%1,%2,%3};"      \
                 : "+f"((dd)[0]), "+f"((dd)[1]), "+f"((dd)[2]), "+f"((dd)[3]) \
                 : "r"(a0), "r"(a1), "r"(a2), "r"(a3), "r"(b0), "r"(b1))

__global__ __launch_bounds__(256, 3) void hist_kernel(const float* __restrict__ x,
                                                      const float* __restrict__ y) {
    extern __shared__ char smem[];
    const uint32_t sb = s2u(smem);
    float* u_s = (float*)(smem + UO);
    float* v_s = (float*)(smem + VO);
    float* w_s = (float*)(smem + WO);

    const int bid   = blockIdx.x;
    const int img   = bid / (NB * 3 * CHUNKS);
    const int rem   = bid % (NB * 3 * CHUNKS);
    const int b     = rem / (3 * CHUNKS);
    const int rem2  = rem % (3 * CHUNKS);
    const int ch    = rem2 / CHUNKS;
    const int chunk = rem2 % CHUNKS;

    const float* base = img ? y : x;
    const float* pr = base + (size_t)(b * 3 + 0) * NPIX + chunk * CHUNK_PIX;
    const float* pg = base + (size_t)(b * 3 + 1) * NPIX + chunk * CHUNK_PIX;
    const float* pb = base + (size_t)(b * 3 + 2) * NPIX + chunk * CHUNK_PIX;

    const int t = threadIdx.x;
    const int w = t >> 5;
    const int L = t & 31;
    const float CK = 300.0f / 63.0f;

    // ldmatrix lane addressing (byte units)
    const int mrow  = L & 7;
    const int msel  = L >> 3;
    const uint32_t swz = (uint32_t)(mrow << 4);
    const uint32_t rowA  = (uint32_t)((16 * w + mrow + (msel & 1) * 8) * 128);
    const uint32_t kaddA = (uint32_t)((msel >> 1) * 16);
    const uint32_t rowBb = (uint32_t)(((msel >> 1) * 8 + mrow) * 128);
    const uint32_t kaddB = (uint32_t)((msel & 1) * 16);
    // eval store addressing
    const uint32_t fourL = (uint32_t)(4 * L);
    const uint32_t wrow  = (uint32_t)(w * 8 * 128);

    const ull K50  = 0x4248000042480000ull;   // {50, 50}
    const ull ONE2 = 0x3F8000003F800000ull;   // {1, 1}

    float d[8][4];
#pragma unroll
    for (int nt = 0; nt < 8; ++nt)
#pragma unroll
        for (int i = 0; i < 4; ++i) d[nt][i] = 0.0f;

    auto ev1 = [&](int jj, ull Un, ull Vn, float wnx, float wny,
                   uint32_t aB, uint32_t bB) {
        const float c50 = (float)(w * 8 + jj) * CK - 150.0f;
        ull C2; DUPU(C2, __float_as_uint(-c50));
        const uint32_t ro = wrow + (uint32_t)(jj * 128) + (fourL ^ (uint32_t)(jj << 4));
        ull T, S; uint32_t s0i, s1i;
        // A side (u, weighted) : fp16 hi/lo split
        F2FMA(T, Un, K50, C2);
        F2FMA(S, T, T, ONE2);
        UNPK(s0i, s1i, S);
        float a0 = frcp(__uint_as_float(s0i)) * wnx;
        float a1 = frcp(__uint_as_float(s1i)) * wny;
        uint32_t ha = packh2(a0, a1);
        float2 hf = unpackh2(ha);
        uint32_t la = packh2(a0 - hf.x, a1 - hf.y);
        STS32(aB + ro, ha);
        STS32(aB + 64 * 128 + ro, la);
        // B side (v) : single fp16
        F2FMA(T, Vn, K50, C2);
        F2FMA(S, T, T, ONE2);
        UNPK(s0i, s1i, S);
        uint32_t hb = packh2(frcp(__uint_as_float(s0i)), frcp(__uint_as_float(s1i)));
        STS32(bB + ro, hb);
    };

    auto mma_s = [&](int s, uint32_t aB, uint32_t bB) {
        const uint32_t ca = (uint32_t)(s * 32);
        uint32_t a[4], bf_[4];
        LDSM4(a, aB + rowA + ((ca + kaddA) ^ swz));
#pragma unroll
        for (int ntp = 0; ntp < 4; ++ntp) {
            LDSM4(bf_, bB + (uint32_t)(ntp * 16 * 128) + rowBb + ((ca + kaddB) ^ swz));
            MMA(d[2 * ntp],     a[0], a[1], a[2], a[3], bf_[0], bf_[1]);
            MMA(d[2 * ntp + 1], a[0], a[1], a[2], a[3], bf_[2], bf_[3]);
        }
    };

    for (int sg = 0; sg < CHUNK_PIX / SG_PIX; ++sg) {
        __syncthreads();
#pragma unroll
        for (int q = 0; q < SG_PIX / 256; ++q) {
            const int p   = t + 256 * q;
            const int pix = sg * SG_PIX + p;
            float r  = pr[pix] + 1e-6f;
            float g  = pg[pix] + 1e-6f;
            float bl = pb[pix] + 1e-6f;
            float lr = __logf(r), lg = __logf(g), lb = __logf(bl);
            float iy = sqrtf(fmaf(r, r, fmaf(g, g, bl * bl)));
            float uu, vv;
            if (ch == 0)      { uu = lr - lg; vv = lr - lb; }
            else if (ch == 1) { uu = lg - lr; vv = lg - lb; }
            else              { uu = lb - lr; vv = lb - lg; }
            u_s[p] = uu; v_s[p] = vv; w_s[p] = iy;
        }
        __syncthreads();

        // prologue: eval window 0 into buffer 0
        {
            ull Un = *(const ull*)&u_s[2 * L];
            ull Vn = *(const ull*)&v_s[2 * L];
            float2 wp = *(const float2*)&w_s[2 * L];
            const uint32_t aB = sb + AO(0), bB = sb + BO(0);
#pragma unroll
            for (int jj = 0; jj < 8; ++jj) ev1(jj, Un, Vn, wp.x, wp.y, aB, bB);
        }
        __syncthreads();

        for (int tt = 0; tt < NWIN; ++tt) {
            const uint32_t cb = (uint32_t)(tt & 1);
            const uint32_t nb_ = cb ^ 1u;
            const uint32_t aB  = sb + AO(cb),  bB  = sb + BO(cb);
            const uint32_t aBn = sb + AO(nb_), bBn = sb + BO(nb_);
            const bool have_next = (tt + 1 < NWIN);
            ull Un = 0, Vn = 0; float2 wp = make_float2(0.f, 0.f);
            if (have_next) {
                const int px0 = (tt + 1) * WIN;
                Un = *(const ull*)&u_s[px0 + 2 * L];
                Vn = *(const ull*)&v_s[px0 + 2 * L];
                wp = *(const float2*)&w_s[px0 + 2 * L];
            }
#pragma unroll
            for (int s = 0; s < 4; ++s) {
                if (have_next) {
                    ev1(2 * s,     Un, Vn, wp.x, wp.y, aBn, bBn);
                    ev1(2 * s + 1, Un, Vn, wp.x, wp.y, aBn, bBn);
                }
                mma_s(s, aB, bB);
            }
            __syncthreads();
        }
    }

    // ---- epilogue: fold D[u] + D[u+64], write block partial ----
    float* epil = (float*)(smem + EPIL);
    const int rg = L >> 2;
    const int cg = (L & 3) * 2;
    if (w >= 4) {
        const int r0 = 16 * (w - 4) + rg;
#pragma unroll
        for (int nt = 0; nt < 8; ++nt) {
            const int c = nt * 8 + cg;
            epil[r0 * 64 + c]           = d[nt][0];
            epil[r0 * 64 + c + 1]       = d[nt][1];
            epil[(r0 + 8) * 64 + c]     = d[nt][2];
            epil[(r0 + 8) * 64 + c + 1] = d[nt][3];
        }
    }
    __syncthreads();
    if (w < 4) {
        const int r0 = 16 * w + rg;
        float* out = g_part + (size_t)bid * (DH * DH);
#pragma unroll
        for (int nt = 0; nt < 8; ++nt) {
            const int c = nt * 8 + cg;
            out[r0 * 64 + c]           = d[nt][0] + epil[r0 * 64 + c];
            out[r0 * 64 + c + 1]       = d[nt][1] + epil[r0 * 64 + c + 1];
            out[(r0 + 8) * 64 + c]     = d[nt][2] + epil[(r0 + 8) * 64 + c];
            out[(r0 + 8) * 64 + c + 1] = d[nt][3] + epil[(r0 + 8) * 64 + c + 1];
        }
    }
}

// 192 blocks: (gidx, quarter). One float4 per thread, 64 chunk partials.
__global__ __launch_bounds__(256) void reduce_kernel() {
    const int g = blockIdx.x >> 2;       // 0..47
    const int q = blockIdx.x & 3;        // 0..3
    const int t = threadIdx.x;
    const int bin4 = q * 1024 + t * 4;   // bin index (float4 granularity)
    float4 a4 = make_float4(0.f, 0.f, 0.f, 0.f);
#pragma unroll 16
    for (int c = 0; c < CHUNKS; ++c) {
        float4 v = *(const float4*)&g_part[(size_t)(g * CHUNKS + c) * (DH * DH) + bin4];
        a4.x += v.x; a4.y += v.y; a4.z += v.z; a4.w += v.w;
    }
    *(float4*)&g_hist[(size_t)g * (DH * DH) + bin4] = a4;
    // block total
    float tot = a4.x + a4.y + a4.z + a4.w;
#pragma unroll
    for (int s2 = 16; s2 > 0; s2 >>= 1)
        tot += __shfl_xor_sync(0xFFFFFFFFu, tot, s2);
    __shared__ float red[8];
    if ((t & 31) == 0) red[t >> 5] = tot;
    __syncthreads();
    if (t == 0) {
        float s = 0.0f;
#pragma unroll
        for (int i = 0; i < 8; ++i) s += red[i];
        g_bsum[blockIdx.x] = s;
    }
}

// single block: 8 warps, warp b handles batch b; thread 0 sums.
__global__ __launch_bounds__(256) void final_kernel(float* __restrict__ out) {
    __shared__ float invtot[16];
    __shared__ float hb[NB];
    const int t = threadIdx.x;
    const int w = t >> 5;
    const int L = t & 31;
    if (t < 16) {
        const int img = t >> 3, b = t & 7;
        const int g0 = (img * NB + b) * 3;     // 3 hists, 4 quarters each
        float s = 0.0f;
#pragma unroll
        for (int k = 0; k < 12; ++k) s += g_bsum[g0 * 4 + k];
        invtot[t] = 1.0f / s;
    }
    __syncthreads();
    {
        const int b = w;
        const float itx = invtot[b];
        const float ity = invtot[8 + b];
        float local = 0.0f;
        for (int idx = L; idx < 3 * DH * DH; idx += 32) {
            const int ch = idx >> 12, bin = idx & 4095;
            float xh = g_hist[(size_t)(b * 3 + ch) * (DH * DH) + bin];
            float yh = g_hist[(size_t)((NB + b) * 3 + ch) * (DH * DH) + bin];
            float dd = sqrtf(yh * ity) - sqrtf(xh * itx);
            local = fmaf(dd, dd, local);
        }
#pragma unroll
        for (int s2 = 16; s2 > 0; s2 >>= 1)
            local += __shfl_xor_sync(0xFFFFFFFFu, local, s2);
        if (L == 0) hb[b] = sqrtf(local * 0.5f);
    }
    __syncthreads();
    if (t == 0) {
        float m = 0.0f;
#pragma unroll
        for (int b = 0; b < NB; ++b) m += hb[b];
        out[0] = m * (1.0f / (float)NB);
    }
}

extern "C" void kernel_launch(void* const* d_in, const int* in_sizes, int n_in,
                              void* d_out, int out_size) {
    const float* x = (const float*)d_in[0];
    const float* y = (const float*)d_in[1];
    cudaFuncSetAttribute(hist_kernel, cudaFuncAttributeMaxDynamicSharedMemorySize,
                         SMEM_BYTES);
    hist_kernel<<<TOT_BLOCKS, 256, SMEM_BYTES>>>(x, y);
    reduce_kernel<<<NHIST * 4, 256>>>();
    final_kernel<<<1, 256>>>((float*)d_out);
}

// round 13
// speedup vs baseline: 1.0173x; 1.0173x over previous
#include <cuda_runtime.h>
#include <cuda_fp16.h>
#include <cstdint>
#include <math.h>

// ---------------------------------------------------------------------------
// ColorHistogramMatchingLoss — R12
// fp16 HMMA histogram GEMM (R9 mainloop, measured 216.8us). Tail rebuilt:
// no 50MB partials (R9 tail ~150us), no scalar atomics (R8 tail ~125us).
// Epilogue folds D into one smem 64x64 tile and issues red.global.add.v4.f32
// (3.1M v4 ops total, ~4x fewer than R8) straight into g_hist.
// ---------------------------------------------------------------------------

#define NB        8
#define DH        64
#define CHUNKS    64
#define CHUNK_PIX 1024
#define SG_PIX    512
#define WIN       64
#define NWIN      (SG_PIX / WIN)      // 8
#define NPIX      65536
#define TOT_BLOCKS (2 * NB * 3 * CHUNKS)   // 3072
#define NHIST     (2 * NB * 3)             // 48

__device__ float g_hist[(size_t)NHIST * DH * DH];
__device__ float g_tot[NHIST];

typedef unsigned long long ull;

// byte offsets in dynamic smem
#define UO 0
#define VO 2048
#define WO 4096
#define AO(bf) (6144 + (bf) * 24576)            // 128 rows x 128B = 16KB
#define BO(bf) (6144 + (bf) * 24576 + 16384)    // 64 rows x 128B = 8KB
#define EPIL   AO(0)
#define SMEM_BYTES (6144 + 2 * 24576)           // 55296

__device__ __forceinline__ uint32_t s2u(const void* p) {
    uint32_t a;
    asm("{ .reg .u64 t; cvta.to.shared.u64 t, %1; cvt.u32.u64 %0, t; }"
        : "=r"(a) : "l"(p));
    return a;
}
__device__ __forceinline__ float frcp(float x) {
    float r; asm("rcp.approx.ftz.f32 %0, %1;" : "=f"(r) : "f"(x)); return r;
}
__device__ __forceinline__ uint32_t packh2(float lo, float hi) {
    __half2 h = __floats2half2_rn(lo, hi);
    return *reinterpret_cast<uint32_t*>(&h);
}
__device__ __forceinline__ float2 unpackh2(uint32_t u) {
    __half2 h = *reinterpret_cast<__half2*>(&u);
    return __half22float2(h);
}
#define F2FMA(d, a, b, c) \
    asm("fma.rn.f32x2 %0, %1, %2, %3;" : "=l"(d) : "l"(a), "l"(b), "l"(c))
#define DUPU(d, u) \
    asm("mov.b64 %0, {%1, %1};" : "=l"(d) : "r"(u))
#define UNPK(lo, hi, v) \
    asm("mov.b64 {%0, %1}, %2;" : "=r"(lo), "=r"(hi) : "l"(v))

#define LDSM4(r, addr)                                                        \
    asm volatile("ldmatrix.sync.aligned.m8n8.x4.shared.b16 {%0,%1,%2,%3}, [%4];" \
                 : "=r"((r)[0]), "=r"((r)[1]), "=r"((r)[2]), "=r"((r)[3])     \
                 : "r"(addr))
#define STS32(addr, v) \
    asm volatile("st.shared.b32 [%0], %1;" :: "r"(addr), "r"(v) : "memory")

#define MMA(dd, a0, a1, a2, a3, b0, b1)                                       \
    asm volatile("mma.sync.aligned.m16n8k16.row.col.f32.f16.f16.f32 "         \
                 "{%0,%1,%2,%3}, {%4,%5,%6,%7}, {%8,%9}, {%0,%1,%2,%3};"      \
                 : "+f"((dd)[0]), "+f"((dd)[1]), "+f"((dd)[2]), "+f"((dd)[3]) \
                 : "r"(a0), "r"(a1), "r"(a2), "r"(a3), "r"(b0), "r"(b1))

__global__ __launch_bounds__(256) void zero_kernel() {
    const int i = blockIdx.x * 256 + threadIdx.x;
    if (i < NHIST * DH * DH) g_hist[i] = 0.0f;
    if (i < NHIST) g_tot[i] = 0.0f;
}

__global__ __launch_bounds__(256, 3) void hist_kernel(const float* __restrict__ x,
                                                      const float* __restrict__ y) {
    extern __shared__ char smem[];
    const uint32_t sb = s2u(smem);
    float* u_s = (float*)(smem + UO);
    float* v_s = (float*)(smem + VO);
    float* w_s = (float*)(smem + WO);

    const int bid   = blockIdx.x;
    const int img   = bid / (NB * 3 * CHUNKS);
    const int rem   = bid % (NB * 3 * CHUNKS);
    const int b     = rem / (3 * CHUNKS);
    const int rem2  = rem % (3 * CHUNKS);
    const int ch    = rem2 / CHUNKS;
    const int chunk = rem2 % CHUNKS;
    const int gidx  = (img * NB + b) * 3 + ch;

    const float* base = img ? y : x;
    const float* pr = base + (size_t)(b * 3 + 0) * NPIX + chunk * CHUNK_PIX;
    const float* pg = base + (size_t)(b * 3 + 1) * NPIX + chunk * CHUNK_PIX;
    const float* pb = base + (size_t)(b * 3 + 2) * NPIX + chunk * CHUNK_PIX;

    const int t = threadIdx.x;
    const int w = t >> 5;
    const int L = t & 31;
    const float CK = 300.0f / 63.0f;

    // ldmatrix lane addressing (byte units)
    const int mrow  = L & 7;
    const int msel  = L >> 3;
    const uint32_t swz = (uint32_t)(mrow << 4);
    const uint32_t rowA  = (uint32_t)((16 * w + mrow + (msel & 1) * 8) * 128);
    const uint32_t kaddA = (uint32_t)((msel >> 1) * 16);
    const uint32_t rowBb = (uint32_t)(((msel >> 1) * 8 + mrow) * 128);
    const uint32_t kaddB = (uint32_t)((msel & 1) * 16);
    // eval store addressing
    const uint32_t fourL = (uint32_t)(4 * L);
    const uint32_t wrow  = (uint32_t)(w * 8 * 128);

    const ull K50  = 0x4248000042480000ull;   // {50, 50}
    const ull ONE2 = 0x3F8000003F800000ull;   // {1, 1}

    float d[8][4];
#pragma unroll
    for (int nt = 0; nt < 8; ++nt)
#pragma unroll
        for (int i = 0; i < 4; ++i) d[nt][i] = 0.0f;

    auto ev1 = [&](int jj, ull Un, ull Vn, float wnx, float wny,
                   uint32_t aB, uint32_t bB) {
        const float c50 = (float)(w * 8 + jj) * CK - 150.0f;
        ull C2; DUPU(C2, __float_as_uint(-c50));
        const uint32_t ro = wrow + (uint32_t)(jj * 128) + (fourL ^ (uint32_t)(jj << 4));
        ull T, S; uint32_t s0i, s1i;
        // A side (u, weighted) : fp16 hi/lo split
        F2FMA(T, Un, K50, C2);
        F2FMA(S, T, T, ONE2);
        UNPK(s0i, s1i, S);
        float a0 = frcp(__uint_as_float(s0i)) * wnx;
        float a1 = frcp(__uint_as_float(s1i)) * wny;
        uint32_t ha = packh2(a0, a1);
        float2 hf = unpackh2(ha);
        uint32_t la = packh2(a0 - hf.x, a1 - hf.y);
        STS32(aB + ro, ha);
        STS32(aB + 64 * 128 + ro, la);
        // B side (v) : single fp16
        F2FMA(T, Vn, K50, C2);
        F2FMA(S, T, T, ONE2);
        UNPK(s0i, s1i, S);
        uint32_t hb = packh2(frcp(__uint_as_float(s0i)), frcp(__uint_as_float(s1i)));
        STS32(bB + ro, hb);
    };

    auto mma_s = [&](int s, uint32_t aB, uint32_t bB) {
        const uint32_t ca = (uint32_t)(s * 32);
        uint32_t a[4], bf_[4];
        LDSM4(a, aB + rowA + ((ca + kaddA) ^ swz));
#pragma unroll
        for (int ntp = 0; ntp < 4; ++ntp) {
            LDSM4(bf_, bB + (uint32_t)(ntp * 16 * 128) + rowBb + ((ca + kaddB) ^ swz));
            MMA(d[2 * ntp],     a[0], a[1], a[2], a[3], bf_[0], bf_[1]);
            MMA(d[2 * ntp + 1], a[0], a[1], a[2], a[3], bf_[2], bf_[3]);
        }
    };

    for (int sg = 0; sg < CHUNK_PIX / SG_PIX; ++sg) {
        __syncthreads();
#pragma unroll
        for (int q = 0; q < SG_PIX / 256; ++q) {
            const int p   = t + 256 * q;
            const int pix = sg * SG_PIX + p;
            float r  = pr[pix] + 1e-6f;
            float g  = pg[pix] + 1e-6f;
            float bl = pb[pix] + 1e-6f;
            float lr = __logf(r), lg = __logf(g), lb = __logf(bl);
            float iy = sqrtf(fmaf(r, r, fmaf(g, g, bl * bl)));
            float uu, vv;
            if (ch == 0)      { uu = lr - lg; vv = lr - lb; }
            else if (ch == 1) { uu = lg - lr; vv = lg - lb; }
            else              { uu = lb - lr; vv = lb - lg; }
            u_s[p] = uu; v_s[p] = vv; w_s[p] = iy;
        }
        __syncthreads();

        // prologue: eval window 0 into buffer 0
        {
            ull Un = *(const ull*)&u_s[2 * L];
            ull Vn = *(const ull*)&v_s[2 * L];
            float2 wp = *(const float2*)&w_s[2 * L];
            const uint32_t aB = sb + AO(0), bB = sb + BO(0);
#pragma unroll
            for (int jj = 0; jj < 8; ++jj) ev1(jj, Un, Vn, wp.x, wp.y, aB, bB);
        }
        __syncthreads();

        for (int tt = 0; tt < NWIN; ++tt) {
            const uint32_t cb = (uint32_t)(tt & 1);
            const uint32_t nb_ = cb ^ 1u;
            const uint32_t aB  = sb + AO(cb),  bB  = sb + BO(cb);
            const uint32_t aBn = sb + AO(nb_), bBn = sb + BO(nb_);
            const bool have_next = (tt + 1 < NWIN);
            ull Un = 0, Vn = 0; float2 wp = make_float2(0.f, 0.f);
            if (have_next) {
                const int px0 = (tt + 1) * WIN;
                Un = *(const ull*)&u_s[px0 + 2 * L];
                Vn = *(const ull*)&v_s[px0 + 2 * L];
                wp = *(const float2*)&w_s[px0 + 2 * L];
            }
#pragma unroll
            for (int s = 0; s < 4; ++s) {
                if (have_next) {
                    ev1(2 * s,     Un, Vn, wp.x, wp.y, aBn, bBn);
                    ev1(2 * s + 1, Un, Vn, wp.x, wp.y, aBn, bBn);
                }
                mma_s(s, aB, bB);
            }
            __syncthreads();
        }
    }

    // ---- epilogue: fold D[u]+D[u+64] into one smem tile, then v4 REDs ----
    float* epil = (float*)(smem + EPIL);
    const int rg = L >> 2;
    const int cg = (L & 3) * 2;
    if (w >= 4) {
        const int r0 = 16 * (w - 4) + rg;
#pragma unroll
        for (int nt = 0; nt < 8; ++nt) {
            const int c = nt * 8 + cg;
            epil[r0 * 64 + c]           = d[nt][0];
            epil[r0 * 64 + c + 1]       = d[nt][1];
            epil[(r0 + 8) * 64 + c]     = d[nt][2];
            epil[(r0 + 8) * 64 + c + 1] = d[nt][3];
        }
    }
    __syncthreads();
    if (w < 4) {
        const int r0 = 16 * w + rg;
#pragma unroll
        for (int nt = 0; nt < 8; ++nt) {
            const int c = nt * 8 + cg;
            epil[r0 * 64 + c]           += d[nt][0];
            epil[r0 * 64 + c + 1]       += d[nt][1];
            epil[(r0 + 8) * 64 + c]     += d[nt][2];
            epil[(r0 + 8) * 64 + c + 1] += d[nt][3];
        }
    }
    __syncthreads();

    float* hdst = g_hist + (size_t)gidx * (DH * DH);
    float tot = 0.0f;
#pragma unroll
    for (int i = 0; i < 4; ++i) {
        const int off = t + i * 256;             // float4 index 0..1023
        float4 v = ((const float4*)epil)[off];
        tot += (v.x + v.y) + (v.z + v.w);
        asm volatile("red.global.add.v4.f32 [%0], {%1, %2, %3, %4};"
                     :: "l"(hdst + off * 4), "f"(v.x), "f"(v.y), "f"(v.z), "f"(v.w)
                     : "memory");
    }
#pragma unroll
    for (int s2 = 16; s2 > 0; s2 >>= 1)
        tot += __shfl_xor_sync(0xFFFFFFFFu, tot, s2);
    __shared__ float redsum[8];
    if (L == 0) redsum[w] = tot;
    __syncthreads();
    if (t == 0) {
        float s = 0.0f;
#pragma unroll
        for (int i = 0; i < 8; ++i) s += redsum[i];
        atomicAdd(&g_tot[gidx], s);
    }
}

// single block: 8 warps, warp b handles batch b; thread 0 sums.
__global__ __launch_bounds__(256) void final_kernel(float* __restrict__ out) {
    __shared__ float invtot[16];
    __shared__ float hb[NB];
    const int t = threadIdx.x;
    const int w = t >> 5;
    const int L = t & 31;
    if (t < 16) {
        const int img = t >> 3, b = t & 7;
        const int g0 = (img * NB + b) * 3;
        invtot[t] = 1.0f / (g_tot[g0] + g_tot[g0 + 1] + g_tot[g0 + 2]);
    }
    __syncthreads();
    {
        const int b = w;
        const float itx = invtot[b];
        const float ity = invtot[8 + b];
        float local = 0.0f;
        for (int idx = L; idx < 3 * DH * DH; idx += 32) {
            const int ch = idx >> 12, bin = idx & 4095;
            float xh = g_hist[(size_t)(b * 3 + ch) * (DH * DH) + bin];
            float yh = g_hist[(size_t)((NB + b) * 3 + ch) * (DH * DH) + bin];
            float dd = sqrtf(yh * ity) - sqrtf(xh * itx);
            local = fmaf(dd, dd, local);
        }
#pragma unroll
        for (int s2 = 16; s2 > 0; s2 >>= 1)
            local += __shfl_xor_sync(0xFFFFFFFFu, local, s2);
        if (L == 0) hb[b] = sqrtf(local * 0.5f);
    }
    __syncthreads();
    if (t == 0) {
        float m = 0.0f;
#pragma unroll
        for (int b = 0; b < NB; ++b) m += hb[b];
        out[0] = m * (1.0f / (float)NB);
    }
}

extern "C" void kernel_launch(void* const* d_in, const int* in_sizes, int n_in,
                              void* d_out, int out_size) {
    const float* x = (const float*)d_in[0];
    const float* y = (const float*)d_in[1];
    cudaFuncSetAttribute(hist_kernel, cudaFuncAttributeMaxDynamicSharedMemorySize,
                         SMEM_BYTES);
    zero_kernel<<<(NHIST * DH * DH + 255) / 256, 256>>>();
    hist_kernel<<<TOT_BLOCKS, 256, SMEM_BYTES>>>(x, y);
    final_kernel<<<1, 256>>>((float*)d_out);
}